// round 5
// baseline (speedup 1.0000x reference)
#include <cuda_runtime.h>

// LSTM: B x T x I -> last hidden -> FC.  I=4, H=8, O=1, T=512.
// Round-5: h exchange via shared memory (1 STS + syncwarp + 2 LDS.128) instead
// of 8 broadcast shuffles -> MIO ops/step 11 -> 4 (theory: SHFL pipe saturation
// explains round 4's 385-cyc step period vs 177-cyc issue demand).
// fma2 packing switched from gate-pairs to k-pairs: h/x arrive as natural
// (even,odd) register pairs, eliminating all dup2 movs; per-row horizontal add.
// Kept: tanh.approx, folded 0.5 sigmoid scales, 4-deep x prefetch.

#define T_SEQ 512
#define IDIM  4
#define HDIM  8

typedef unsigned long long u64;

__device__ __forceinline__ u64 pack2(float a, float b) {
    u64 r; asm("mov.b64 %0,{%1,%2};" : "=l"(r) : "f"(a), "f"(b)); return r;
}
__device__ __forceinline__ float2 unpack2(u64 v) {
    float2 r; asm("mov.b64 {%0,%1},%2;" : "=f"(r.x), "=f"(r.y) : "l"(v)); return r;
}
__device__ __forceinline__ u64 fma2(u64 a, u64 b, u64 c) {
    u64 d; asm("fma.rn.f32x2 %0,%1,%2,%3;" : "=l"(d) : "l"(a), "l"(b), "l"(c)); return d;
}
__device__ __forceinline__ float hadd2(u64 v) {
    float2 t = unpack2(v); return t.x + t.y;
}
__device__ __forceinline__ float tanh_fast(float x) {
    float y; asm("tanh.approx.f32 %0,%1;" : "=f"(y) : "f"(x)); return y;
}

struct LaneW {
    // per gate row (i,f,g,o owned by this lane's unit): k-paired weights
    u64 wih[4][2];    // input weights  (pairs over IDIM)
    u64 whh[4][4];    // recurrent weights (pairs over HDIM)
    u64 bias[4];      // (bias, 0)
};

__global__ __launch_bounds__(64)
void lstm_fused_kernel(const float* __restrict__ x,
                       const float* __restrict__ W_ih,
                       const float* __restrict__ W_hh,
                       const float* __restrict__ b_ih,
                       const float* __restrict__ b_hh,
                       const float* __restrict__ W_fc,
                       const float* __restrict__ b_fc,
                       float* __restrict__ out,
                       int B)
{
    const int tid  = threadIdx.x;
    const int lane = tid & 31;
    const int wrp  = tid >> 5;                      // warp within block (0..1)
    const int j    = tid & 7;                       // hidden unit owned by this lane
    const int grp  = (tid >> 3) & 3;                // 8-lane group within warp
    int b = blockIdx.x * 8 + (tid >> 3);            // batch element
    const bool valid = (b < B);
    if (b >= B) b = B - 1;                          // clamp: keep warp converged

    // h exchange table: per warp, 4 groups x 8 floats = 128B
    __shared__ float htab[2][32];

    // ---- per-lane weights, k-paired; sigmoid rows (i,f,o) pre-scaled by 0.5
    // so sigmoid(z) = 0.5*tanh(acc)+0.5 directly. Gate g (tanh) unscaled.
    LaneW W;
    {
        const float sc[4] = {0.5f, 0.5f, 1.0f, 0.5f};
#pragma unroll
        for (int r = 0; r < 4; ++r) {
            const int row = r * HDIM + j;
            const float s = sc[r];
#pragma unroll
            for (int m = 0; m < 2; ++m)
                W.wih[r][m] = pack2(s * W_ih[row * IDIM + 2 * m],
                                    s * W_ih[row * IDIM + 2 * m + 1]);
#pragma unroll
            for (int m = 0; m < 4; ++m)
                W.whh[r][m] = pack2(s * W_hh[row * HDIM + 2 * m],
                                    s * W_hh[row * HDIM + 2 * m + 1]);
            W.bias[r] = pack2(s * (b_ih[row] + b_hh[row]), 0.0f);
        }
    }

    const float4* __restrict__ xp =
        reinterpret_cast<const float4*>(x) + (size_t)b * T_SEQ;

    float h = 0.0f, c = 0.0f;
    htab[wrp][lane] = 0.0f;                          // h_{-1} = 0
    __syncwarp();

    // rolling 4-step prefetch buffer (covers DRAM miss latency, MLP=4)
    float4 buf0 = xp[0], buf1 = xp[1], buf2 = xp[2], buf3 = xp[3];

    const ulonglong2* __restrict__ hrow =
        reinterpret_cast<const ulonglong2*>(&htab[wrp][grp * 8]);

#pragma unroll 1
    for (int t0 = 0; t0 < T_SEQ; t0 += 4) {
        const int tn = (t0 + 4) & (T_SEQ - 1);      // wraps on last iter (harmless)
        const float4 n0 = xp[tn + 0];
        const float4 n1 = xp[tn + 1];
        const float4 n2 = xp[tn + 2];
        const float4 n3 = xp[tn + 3];

        const float4 bufs[4] = {buf0, buf1, buf2, buf3};
#pragma unroll
        for (int u = 0; u < 4; ++u) {
            const float4 xc = bufs[u];
            const u64 x01 = pack2(xc.x, xc.y);
            const u64 x23 = pack2(xc.z, xc.w);

            // input projection + bias (h-independent)
            u64 acc[4];
#pragma unroll
            for (int r = 0; r < 4; ++r) {
                u64 a = fma2(W.wih[r][0], x01, W.bias[r]);
                acc[r] = fma2(W.wih[r][1], x23, a);
            }

            // fetch h pairs from shared memory (written at end of prev step)
            const ulonglong2 hv0 = hrow[0];          // (h0,h1),(h2,h3)
            const ulonglong2 hv1 = hrow[1];          // (h4,h5),(h6,h7)

#pragma unroll
            for (int r = 0; r < 4; ++r) {
                u64 a = fma2(W.whh[r][0], hv0.x, acc[r]);
                a     = fma2(W.whh[r][1], hv0.y, a);
                a     = fma2(W.whh[r][2], hv1.x, a);
                acc[r]= fma2(W.whh[r][3], hv1.y, a);
            }

            const float zi = hadd2(acc[0]);
            const float zf = hadd2(acc[1]);
            const float zg = hadd2(acc[2]);
            const float zo = hadd2(acc[3]);

            const float ig = fmaf(0.5f, tanh_fast(zi), 0.5f);
            const float fg = fmaf(0.5f, tanh_fast(zf), 0.5f);
            const float gg = tanh_fast(zg);
            const float og = fmaf(0.5f, tanh_fast(zo), 0.5f);
            c = fmaf(fg, c, ig * gg);
            h = og * tanh_fast(c);

            // publish h for next step
            htab[wrp][lane] = h;
            __syncwarp();
        }

        buf0 = n0; buf1 = n1; buf2 = n2; buf3 = n3;
    }

    // ---- FC head: out[b] = sum_j h_j * W_fc[j] + b_fc ----
    float v = h * __ldg(W_fc + j);
    v += __shfl_xor_sync(0xffffffffu, v, 1, 8);
    v += __shfl_xor_sync(0xffffffffu, v, 2, 8);
    v += __shfl_xor_sync(0xffffffffu, v, 4, 8);

    if (valid && j == 0) out[b] = v + __ldg(b_fc);
}

extern "C" void kernel_launch(void* const* d_in, const int* in_sizes, int n_in,
                              void* d_out, int out_size)
{
    const float* x    = (const float*)d_in[0];
    const float* W_ih = (const float*)d_in[1];
    const float* W_hh = (const float*)d_in[2];
    const float* b_ih = (const float*)d_in[3];
    const float* b_hh = (const float*)d_in[4];
    const float* W_fc = (const float*)d_in[5];
    const float* b_fc = (const float*)d_in[6];
    float* out = (float*)d_out;

    const int B = in_sizes[0] / (T_SEQ * IDIM);     // 8192 here
    const int groups_per_block = 8;                 // 64 threads / 8 lanes
    const int grid = (B + groups_per_block - 1) / groups_per_block;

    lstm_fused_kernel<<<grid, 64>>>(x, W_ih, W_hh, b_ih, b_hh, W_fc, b_fc, out, B);
}